// round 13
// baseline (speedup 1.0000x reference)
#include <cuda_runtime.h>
#include <cuda_bf16.h>
#include <stdint.h>
#include <math.h>

#define B 64
#define T 512
#define E 768
#define H 72
#define BT (B*T)

#define NS   48              // k16 steps over K=768
#define NG   216             // total output cols (3*72)
#define WPIDX (NG*NS*4)      // uint4 count in packed W
#define HPAIR 36             // h-pairs per row for packed Q/K
#define TPAIR 256            // token-pairs per batch for packed V

#define QSCALE 0.11785113019775793f   // 1/sqrt(72)

// Scratch (static device globals -- no allocation in kernel_launch)
__device__ float g_V[BT*H];
__device__ unsigned g_Qp_hi[BT*HPAIR];
__device__ unsigned g_Qp_lo[BT*HPAIR];
__device__ unsigned g_Kp_hi[BT*HPAIR];
__device__ unsigned g_Kp_lo[BT*HPAIR];
// V packed transposed: [b][pair p][n]  (p = token pair 0..255, n = 0..71)
__device__ unsigned g_Vp_hi[B*TPAIR*H];
__device__ unsigned g_Vp_lo[B*TPAIR*H];
// Packed W fragments: uint4 at index ng*192 + s*4 + c2g
__device__ uint4 g_Wp[WPIDX];

__device__ __forceinline__ void mma16816(float* c, const unsigned* a, const unsigned* b)
{
    asm volatile(
        "mma.sync.aligned.m16n8k16.row.col.f32.bf16.bf16.f32 "
        "{%0,%1,%2,%3}, {%4,%5,%6,%7}, {%8,%9}, {%0,%1,%2,%3};\n"
        : "+f"(c[0]), "+f"(c[1]), "+f"(c[2]), "+f"(c[3])
        : "r"(a[0]), "r"(a[1]), "r"(a[2]), "r"(a[3]), "r"(b[0]), "r"(b[1]));
}

// slow-path packers (cold code: prep/vpack/epilogues)
__device__ __forceinline__ unsigned pack_hi2(float a, float b)
{
    __nv_bfloat162 p = __halves2bfloat162(__float2bfloat16(a), __float2bfloat16(b));
    return *reinterpret_cast<unsigned*>(&p);
}
__device__ __forceinline__ unsigned pack_lo2(float a, float b)
{
    __nv_bfloat16 ha = __float2bfloat16(a);
    __nv_bfloat16 hb = __float2bfloat16(b);
    __nv_bfloat162 p = __halves2bfloat162(
        __float2bfloat16(a - __bfloat162float(ha)),
        __float2bfloat16(b - __bfloat162float(hb)));
    return *reinterpret_cast<unsigned*>(&p);
}

// fast hi/lo split: packed cvt + shift/mask residual (6 instr)
__device__ __forceinline__ void split2f(float v0, float v1, unsigned& hi, unsigned& lo)
{
    unsigned h;
    asm("cvt.rn.bf16x2.f32 %0, %1, %2;" : "=r"(h) : "f"(v1), "f"(v0));
    float h0 = __uint_as_float(h << 16);
    float h1 = __uint_as_float(h & 0xffff0000u);
    float r0 = v0 - h0;
    float r1 = v1 - h1;
    asm("cvt.rn.bf16x2.f32 %0, %1, %2;" : "=r"(lo) : "f"(r1), "f"(r0));
    hi = h;
}
__device__ __forceinline__ void split2(float2 v, unsigned& hi, unsigned& lo)
{
    split2f(v.x, v.y, hi, lo);
}

__device__ __forceinline__ void cp16(unsigned smaddr, const void* gptr)
{
    asm volatile("cp.async.cg.shared.global [%0], [%1], 16;\n"
                 :: "r"(smaddr), "l"(gptr));
}

// ---------------------------------------------------------------------------
// prep_w: pack Wk|Wq|Wv into mma B-fragment layout (global)
// ---------------------------------------------------------------------------
__global__ __launch_bounds__(256) void prep_w(
    const float* __restrict__ Wk,
    const float* __restrict__ Wq,
    const float* __restrict__ Wv)
{
    int idx = blockIdx.x * 256 + threadIdx.x;
    if (idx >= WPIDX) return;
    int c2g = idx & 3;
    int s   = (idx >> 2) % NS;
    int ng  = idx / (4 * NS);
    int which = ng / H;
    int n     = ng - which * H;
    const float* __restrict__ W = (which == 0) ? Wk : ((which == 1) ? Wq : Wv);
    int k = s * 16 + c2g * 2;
    float w00 = W[(size_t)(k + 0) * H + n];
    float w01 = W[(size_t)(k + 1) * H + n];
    float w10 = W[(size_t)(k + 8) * H + n];
    float w11 = W[(size_t)(k + 9) * H + n];
    uint4 p;
    p.x = pack_hi2(w00, w01);
    p.y = pack_hi2(w10, w11);
    p.z = pack_lo2(w00, w01);
    p.w = pack_lo2(w10, w11);
    g_Wp[idx] = p;
}

// ---------------------------------------------------------------------------
// Fused projection GEMM (K,Q,V), v4: smem-staged B fragments.
// CTA = 64 rows, 8 warps: warps 0-3 rows (w&3)*16 nt 0..13; warps 4-7 nt 13..26.
// B: 4-stage cp.async ring, 13824B/stage (one k16-step: 216 ng x 4 c2g x 16B).
// Fragments via conflict-free LDS.128. acc[14][4], <=128 regs, 2 CTAs/SM.
// ---------------------------------------------------------------------------
#define PSTG_B 13824
#define PROJ_SMEM (4 * PSTG_B)   // 55296

__global__ __launch_bounds__(256, 2) void proj_kernel(const float* __restrict__ x)
{
    extern __shared__ char psm[];
    const unsigned psmb = (unsigned)__cvta_generic_to_shared(psm);

    const int t    = threadIdx.x;
    const int wid  = t >> 5;
    const int lane = t & 31;
    const int g    = lane >> 2;
    const int c2   = (lane & 3) * 2;
    const int c2g  = lane & 3;

    const int ntbase = (wid >> 2) * 13;          // 0 or 13
    const int m0 = blockIdx.x * 64 + (wid & 3) * 16;
    const float* __restrict__ pA = x + (size_t)(m0 + g) * E;
    const float* __restrict__ pB = x + (size_t)(m0 + g + 8) * E;

    float acc[14][4];
    #pragma unroll
    for (int j = 0; j < 14; j++)
        #pragma unroll
        for (int i = 0; i < 4; i++) acc[j][i] = 0.f;

    // stage filler: one k16-step of all 216 B rows, hi/lo packed uint4
    auto fill = [&](int stage, int s) {
        const unsigned dst = psmb + stage * PSTG_B;
        for (int i = t; i < 864; i += 256) {
            const int cc = i & 3, ng = i >> 2;
            cp16(dst + ng * 64 + cc * 16, g_Wp + ng * 192 + s * 4 + cc);
        }
    };

    // prologue: 3 stages in flight
    fill(0, 0); asm volatile("cp.async.commit_group;\n");
    fill(1, 1); asm volatile("cp.async.commit_group;\n");
    fill(2, 2); asm volatile("cp.async.commit_group;\n");

    float2 cur[4];
    cur[0] = *reinterpret_cast<const float2*>(pA + c2);
    cur[1] = *reinterpret_cast<const float2*>(pB + c2);
    cur[2] = *reinterpret_cast<const float2*>(pA + 8 + c2);
    cur[3] = *reinterpret_cast<const float2*>(pB + 8 + c2);

    for (int s = 0; s < NS; s++) {
        asm volatile("cp.async.wait_group 2;\n");
        __syncthreads();

        float2 nxt[4];
        if (s < NS - 1) {
            const int k = (s + 1) * 16;
            nxt[0] = *reinterpret_cast<const float2*>(pA + k + c2);
            nxt[1] = *reinterpret_cast<const float2*>(pB + k + c2);
            nxt[2] = *reinterpret_cast<const float2*>(pA + k + 8 + c2);
            nxt[3] = *reinterpret_cast<const float2*>(pB + k + 8 + c2);
        }

        unsigned ahi[4], alo[4];
        split2(cur[0], ahi[0], alo[0]);
        split2(cur[1], ahi[1], alo[1]);
        split2(cur[2], ahi[2], alo[2]);
        split2(cur[3], ahi[3], alo[3]);

        const char* __restrict__ stp = psm + (s & 3) * PSTG_B + c2g * 16 + g * 64;
        #pragma unroll
        for (int j = 0; j < 14; j++) {
            const int nt = ntbase + j;
            uint4 bw = *reinterpret_cast<const uint4*>(stp + nt * 512);
            unsigned bhi[2] = { bw.x, bw.y };
            unsigned blo[2] = { bw.z, bw.w };
            mma16816(acc[j], ahi, bhi);
            mma16816(acc[j], ahi, blo);
            mma16816(acc[j], alo, bhi);
        }

        if (s + 3 < NS) fill((s + 3) & 3, s + 3);
        asm volatile("cp.async.commit_group;\n");

        cur[0] = nxt[0]; cur[1] = nxt[1]; cur[2] = nxt[2]; cur[3] = nxt[3];
    }

    // Epilogue: nt_global = ntbase + j. K: 0..8, Q: 9..17 (prescaled), V: 18..26
    const size_t rA = (size_t)(m0 + g);
    const size_t rB = (size_t)(m0 + g + 8);
    #pragma unroll
    for (int j = 0; j < 14; j++) {
        const int ntg   = ntbase + j;
        const int which = ntg / 9;
        const int nb    = ntg - which * 9;
        if (which == 0) {
            const int pp = nb * 4 + c2g;
            unsigned h0, l0v, h1, l1v;
            split2f(acc[j][0], acc[j][1], h0, l0v);
            split2f(acc[j][2], acc[j][3], h1, l1v);
            g_Kp_hi[rA * HPAIR + pp] = h0;
            g_Kp_lo[rA * HPAIR + pp] = l0v;
            g_Kp_hi[rB * HPAIR + pp] = h1;
            g_Kp_lo[rB * HPAIR + pp] = l1v;
        } else if (which == 1) {
            const int pp = nb * 4 + c2g;
            float q0 = acc[j][0] * QSCALE, q1 = acc[j][1] * QSCALE;
            float q2 = acc[j][2] * QSCALE, q3 = acc[j][3] * QSCALE;
            unsigned h0, l0v, h1, l1v;
            split2f(q0, q1, h0, l0v);
            split2f(q2, q3, h1, l1v);
            g_Qp_hi[rA * HPAIR + pp] = h0;
            g_Qp_lo[rA * HPAIR + pp] = l0v;
            g_Qp_hi[rB * HPAIR + pp] = h1;
            g_Qp_lo[rB * HPAIR + pp] = l1v;
        } else {
            const int col = nb * 8 + c2;
            *reinterpret_cast<float2*>(&g_V[rA * H + col]) =
                make_float2(acc[j][0], acc[j][1]);
            *reinterpret_cast<float2*>(&g_V[rB * H + col]) =
                make_float2(acc[j][2], acc[j][3]);
        }
    }
}

// ---------------------------------------------------------------------------
// vpack: fp32 V -> hi/lo bf16x2 token-pairs, TRANSPOSED layout [b][p][n]
// ---------------------------------------------------------------------------
__global__ __launch_bounds__(256) void vpack_kernel()
{
    int idx = blockIdx.x * 256 + threadIdx.x;
    if (idx >= B * TPAIR * H) return;
    int n   = idx % H;
    int rem = idx / H;
    int p   = rem % TPAIR;
    int b   = rem / TPAIR;
    float v0 = g_V[((size_t)b * T + 2 * p)     * H + n];
    float v1 = g_V[((size_t)b * T + 2 * p + 1) * H + n];
    unsigned h, l;
    split2f(v0, v1, h, l);
    g_Vp_hi[idx] = h;
    g_Vp_lo[idx] = l;
}

// ---------------------------------------------------------------------------
// Tensor-core flash attention, smem-staged with cp.async double buffering.
// 128 threads (4 warps), BR=64 (16 rows/warp), BC=64.
// ---------------------------------------------------------------------------
#define STG_U32 9216
#define KOFF_L  2304
#define VOFF_H  4608
#define VOFF_L  6912

__global__ __launch_bounds__(128) void attn_kernel(float* __restrict__ out)
{
    extern __shared__ unsigned smn[];
    const unsigned smbase = (unsigned)__cvta_generic_to_shared(smn);

    const int qt = (int)(gridDim.x - 1 - blockIdx.x);   // heavy tiles first
    const int b  = blockIdx.y;
    const int t  = threadIdx.x;
    const int w    = t >> 5;
    const int lane = t & 31;
    const int g    = lane >> 2;
    const int li   = lane & 3;

    const int row0 = qt * 64 + w * 16;
    const size_t qbase = (size_t)b * T + row0;

    unsigned qhi[5][4], qlo[5][4];
    #pragma unroll
    for (int ks = 0; ks < 5; ks++) {
        if (ks < 4) {
            const int p0 = ks * 8 + li, p1 = ks * 8 + 4 + li;
            qhi[ks][0] = g_Qp_hi[(qbase + g)     * HPAIR + p0];
            qhi[ks][1] = g_Qp_hi[(qbase + g + 8) * HPAIR + p0];
            qhi[ks][2] = g_Qp_hi[(qbase + g)     * HPAIR + p1];
            qhi[ks][3] = g_Qp_hi[(qbase + g + 8) * HPAIR + p1];
            qlo[ks][0] = g_Qp_lo[(qbase + g)     * HPAIR + p0];
            qlo[ks][1] = g_Qp_lo[(qbase + g + 8) * HPAIR + p0];
            qlo[ks][2] = g_Qp_lo[(qbase + g)     * HPAIR + p1];
            qlo[ks][3] = g_Qp_lo[(qbase + g + 8) * HPAIR + p1];
        } else {
            const int p0 = 32 + li;
            qhi[4][0] = g_Qp_hi[(qbase + g)     * HPAIR + p0];
            qhi[4][1] = g_Qp_hi[(qbase + g + 8) * HPAIR + p0];
            qhi[4][2] = 0; qhi[4][3] = 0;
            qlo[4][0] = g_Qp_lo[(qbase + g)     * HPAIR + p0];
            qlo[4][1] = g_Qp_lo[(qbase + g + 8) * HPAIR + p0];
            qlo[4][2] = 0; qlo[4][3] = 0;
        }
    }

    auto fill = [&](int stage, int kt) {
        const unsigned dst = smbase + stage * (STG_U32 * 4);
        const char* sK_h = (const char*)(g_Kp_hi + ((size_t)b * T + kt * 64) * HPAIR);
        const char* sK_l = (const char*)(g_Kp_lo + ((size_t)b * T + kt * 64) * HPAIR);
        const char* sV_h = (const char*)(g_Vp_hi + ((size_t)b * TPAIR + kt * 32) * H);
        const char* sV_l = (const char*)(g_Vp_lo + ((size_t)b * TPAIR + kt * 32) * H);
        for (int i = t; i < 576; i += 128) {
            const int o = i * 16;
            cp16(dst + o,                 sK_h + o);
            cp16(dst + KOFF_L * 4 + o,    sK_l + o);
            cp16(dst + VOFF_H * 4 + o,    sV_h + o);
            cp16(dst + VOFF_L * 4 + o,    sV_l + o);
        }
    };

    fill(0, 0);
    asm volatile("cp.async.commit_group;\n");

    float m0r = -1e30f, m1r = -1e30f, l0 = 0.f, l1 = 0.f;
    float o[9][4];
    #pragma unroll
    for (int j = 0; j < 9; j++)
        #pragma unroll
        for (int i = 0; i < 4; i++) o[j][i] = 0.f;

    for (int kt = 0; kt <= qt; kt++) {
        if (kt < qt) {
            fill((kt + 1) & 1, kt + 1);
            asm volatile("cp.async.commit_group;\n");
            asm volatile("cp.async.wait_group 1;\n");
        } else {
            asm volatile("cp.async.wait_group 0;\n");
        }
        __syncthreads();

        const unsigned* __restrict__ st = smn + (kt & 1) * STG_U32;
        const unsigned* __restrict__ Kh = st;
        const unsigned* __restrict__ Kl = st + KOFF_L;
        const unsigned* __restrict__ Vh = st + VOFF_H;
        const unsigned* __restrict__ Vl = st + VOFF_L;

        float s[8][4];
        #pragma unroll
        for (int nb = 0; nb < 8; nb++)
            #pragma unroll
            for (int i = 0; i < 4; i++) s[nb][i] = 0.f;

        #pragma unroll
        for (int ks = 0; ks < 5; ks++) {
            #pragma unroll
            for (int nb = 0; nb < 8; nb++) {
                const int rk = (nb * 8 + g) * HPAIR;
                unsigned bh[2], bl[2];
                if (ks < 4) {
                    bh[0] = Kh[rk + ks * 8 + li];
                    bh[1] = Kh[rk + ks * 8 + 4 + li];
                    bl[0] = Kl[rk + ks * 8 + li];
                    bl[1] = Kl[rk + ks * 8 + 4 + li];
                } else {
                    bh[0] = Kh[rk + 32 + li]; bh[1] = 0;
                    bl[0] = Kl[rk + 32 + li]; bl[1] = 0;
                }
                mma16816(s[nb], qhi[ks], bh);
                mma16816(s[nb], qhi[ks], bl);
                mma16816(s[nb], qlo[ks], bh);
            }
        }

        if (kt == qt) {
            const int r0g = row0 + g, r1g = row0 + g + 8;
            #pragma unroll
            for (int nb = 0; nb < 8; nb++) {
                const int c = qt * 64 + nb * 8 + 2 * li;
                if (c     > r0g) s[nb][0] = -1e30f;
                if (c + 1 > r0g) s[nb][1] = -1e30f;
                if (c     > r1g) s[nb][2] = -1e30f;
                if (c + 1 > r1g) s[nb][3] = -1e30f;
            }
        }

        float rm0 = -1e30f, rm1 = -1e30f;
        #pragma unroll
        for (int nb = 0; nb < 8; nb++) {
            rm0 = fmaxf(rm0, fmaxf(s[nb][0], s[nb][1]));
            rm1 = fmaxf(rm1, fmaxf(s[nb][2], s[nb][3]));
        }
        rm0 = fmaxf(rm0, __shfl_xor_sync(0xffffffffu, rm0, 1));
        rm0 = fmaxf(rm0, __shfl_xor_sync(0xffffffffu, rm0, 2));
        rm1 = fmaxf(rm1, __shfl_xor_sync(0xffffffffu, rm1, 1));
        rm1 = fmaxf(rm1, __shfl_xor_sync(0xffffffffu, rm1, 2));

        const float mn0 = fmaxf(m0r, rm0);
        const float mn1 = fmaxf(m1r, rm1);
        const float sc0 = __expf(m0r - mn0);
        const float sc1 = __expf(m1r - mn1);

        float rs0 = 0.f, rs1 = 0.f;
        #pragma unroll
        for (int nb = 0; nb < 8; nb++) {
            s[nb][0] = __expf(s[nb][0] - mn0);
            s[nb][1] = __expf(s[nb][1] - mn0);
            s[nb][2] = __expf(s[nb][2] - mn1);
            s[nb][3] = __expf(s[nb][3] - mn1);
            rs0 += s[nb][0] + s[nb][1];
            rs1 += s[nb][2] + s[nb][3];
        }
        rs0 += __shfl_xor_sync(0xffffffffu, rs0, 1);
        rs0 += __shfl_xor_sync(0xffffffffu, rs0, 2);
        rs1 += __shfl_xor_sync(0xffffffffu, rs1, 1);
        rs1 += __shfl_xor_sync(0xffffffffu, rs1, 2);

        l0 = l0 * sc0 + rs0;
        l1 = l1 * sc1 + rs1;
        m0r = mn0; m1r = mn1;

        #pragma unroll
        for (int j = 0; j < 9; j++) {
            o[j][0] *= sc0; o[j][1] *= sc0;
            o[j][2] *= sc1; o[j][3] *= sc1;
        }

        #pragma unroll
        for (int ks = 0; ks < 4; ks++) {
            unsigned ph[4], pl[4];
            split2f(s[2*ks][0],   s[2*ks][1],   ph[0], pl[0]);
            split2f(s[2*ks][2],   s[2*ks][3],   ph[1], pl[1]);
            split2f(s[2*ks+1][0], s[2*ks+1][1], ph[2], pl[2]);
            split2f(s[2*ks+1][2], s[2*ks+1][3], ph[3], pl[3]);

            const int rv0 = (ks * 8 + li) * H;
            const int rv1 = (ks * 8 + 4 + li) * H;
            #pragma unroll
            for (int nb = 0; nb < 9; nb++) {
                const int cn = nb * 8 + g;
                unsigned vh[2] = { Vh[rv0 + cn], Vh[rv1 + cn] };
                unsigned vl[2] = { Vl[rv0 + cn], Vl[rv1 + cn] };
                mma16816(o[nb], ph, vh);
                mma16816(o[nb], ph, vl);
                mma16816(o[nb], pl, vh);
            }
        }
        __syncthreads();
    }

    const float inv0 = 1.f / l0;
    const float inv1 = 1.f / l1;
    float* od0 = out + (qbase + g)     * H;
    float* od1 = out + (qbase + g + 8) * H;
    #pragma unroll
    for (int nb = 0; nb < 9; nb++) {
        const int col = nb * 8 + 2 * li;
        *reinterpret_cast<float2*>(od0 + col) = make_float2(o[nb][0] * inv0, o[nb][1] * inv0);
        *reinterpret_cast<float2*>(od1 + col) = make_float2(o[nb][2] * inv1, o[nb][3] * inv1);
    }
}

// ---------------------------------------------------------------------------
extern "C" void kernel_launch(void* const* d_in, const int* in_sizes, int n_in,
                              void* d_out, int out_size)
{
    const float* x  = (const float*)d_in[0];
    const float* Wk = (const float*)d_in[1];
    const float* Wq = (const float*)d_in[2];
    const float* Wv = (const float*)d_in[3];
    float* out = (float*)d_out;

    prep_w<<<(WPIDX + 255) / 256, 256>>>(Wk, Wq, Wv);

    cudaFuncSetAttribute(proj_kernel, cudaFuncAttributeMaxDynamicSharedMemorySize, PROJ_SMEM);
    proj_kernel<<<BT / 64, 256, PROJ_SMEM>>>(x);

    vpack_kernel<<<(B * TPAIR * H + 255) / 256, 256>>>();

    cudaFuncSetAttribute(attn_kernel, cudaFuncAttributeMaxDynamicSharedMemorySize, 73728);
    attn_kernel<<<dim3(T / 64, B), 128, 73728>>>(out);
}

// round 14
// speedup vs baseline: 1.7031x; 1.7031x over previous
#include <cuda_runtime.h>
#include <cuda_fp16.h>
#include <stdint.h>
#include <math.h>

#define B 64
#define T 512
#define E 768
#define H 72
#define BT (B*T)

#define NS   48              // k16 steps over K=768
#define NG   216             // total output cols (3*72)
#define WPIDX (NG*NS*4)      // uint2 count in packed W
#define HPAIR 36             // h-pairs per row for packed Q/K
#define TPAIR 256            // token-pairs per batch for packed V

#define QSCALE 0.11785113019775793f   // 1/sqrt(72)

// Scratch (static device globals -- no allocation in kernel_launch)
__device__ float g_V[BT*H];
__device__ unsigned g_Qp_hi[BT*HPAIR];   // fp16x2 h-pairs (A operand: hi+lo)
__device__ unsigned g_Qp_lo[BT*HPAIR];
__device__ unsigned g_Kp[BT*HPAIR];      // fp16x2 h-pairs (B operand: hi only)
// V packed transposed: [b][pair p][n] (hi only)
__device__ unsigned g_Vp[B*TPAIR*H];
// Packed W fragments (hi only): uint2 at index ng*192 + s*4 + c2g
__device__ uint2 g_Wp2[WPIDX];

// ---------------------------------------------------------------------------
__device__ __forceinline__ void mmaf16(float* c, const unsigned* a, const unsigned* b)
{
    asm volatile(
        "mma.sync.aligned.m16n8k16.row.col.f32.f16.f16.f32 "
        "{%0,%1,%2,%3}, {%4,%5,%6,%7}, {%8,%9}, {%0,%1,%2,%3};\n"
        : "+f"(c[0]), "+f"(c[1]), "+f"(c[2]), "+f"(c[3])
        : "r"(a[0]), "r"(a[1]), "r"(a[2]), "r"(a[3]), "r"(b[0]), "r"(b[1]));
}

__device__ __forceinline__ unsigned pack_h2(float a, float b)
{
    __half2 h = __floats2half2_rn(a, b);
    return *reinterpret_cast<unsigned*>(&h);
}
// A-operand split: hi = RN(v), lo = RN(v - hi)  (captures v to ~2^-22)
__device__ __forceinline__ void split2h(float v0, float v1, unsigned& hi, unsigned& lo)
{
    __half2 h = __floats2half2_rn(v0, v1);
    float2 hf = __half22float2(h);
    __half2 l = __floats2half2_rn(v0 - hf.x, v1 - hf.y);
    hi = *reinterpret_cast<unsigned*>(&h);
    lo = *reinterpret_cast<unsigned*>(&l);
}

__device__ __forceinline__ void cp16(unsigned smaddr, const void* gptr)
{
    asm volatile("cp.async.cg.shared.global [%0], [%1], 16;\n"
                 :: "r"(smaddr), "l"(gptr));
}

// ---------------------------------------------------------------------------
// prep_w: pack Wk|Wq|Wv (fp16 hi only) into mma B-fragment layout
// ---------------------------------------------------------------------------
__global__ __launch_bounds__(256) void prep_w(
    const float* __restrict__ Wk,
    const float* __restrict__ Wq,
    const float* __restrict__ Wv)
{
    int idx = blockIdx.x * 256 + threadIdx.x;
    if (idx >= WPIDX) return;
    int c2g = idx & 3;
    int s   = (idx >> 2) % NS;
    int ng  = idx / (4 * NS);
    int which = ng / H;
    int n     = ng - which * H;
    const float* __restrict__ W = (which == 0) ? Wk : ((which == 1) ? Wq : Wv);
    int k = s * 16 + c2g * 2;
    uint2 p;
    p.x = pack_h2(W[(size_t)(k + 0) * H + n], W[(size_t)(k + 1) * H + n]);
    p.y = pack_h2(W[(size_t)(k + 8) * H + n], W[(size_t)(k + 9) * H + n]);
    g_Wp2[idx] = p;
}

// ---------------------------------------------------------------------------
// Fused projection GEMM (K,Q,V) — round-7 structure, fp16 2-term.
// CTA = 64 rows, 8 warps. Warps 0-3: rows (w&3)*16, nt 0..13.
//                        Warps 4-7: same rows,      nt 13..26.
// 2 mma per (k-step, tile): Ahi*Bhi + Alo*Bhi. B frag = uint2 (hi only).
// ---------------------------------------------------------------------------
__global__ __launch_bounds__(256, 2) void proj_kernel(const float* __restrict__ x)
{
    const int t    = threadIdx.x;
    const int wid  = t >> 5;
    const int lane = t & 31;
    const int g    = lane >> 2;
    const int c2   = (lane & 3) * 2;
    const int c2g  = lane & 3;

    const int ntbase = (wid >> 2) * 13;          // 0 or 13
    const int m0 = blockIdx.x * 64 + (wid & 3) * 16;
    const float* __restrict__ pA = x + (size_t)(m0 + g) * E;
    const float* __restrict__ pB = x + (size_t)(m0 + g + 8) * E;

    float acc[14][4];
    #pragma unroll
    for (int j = 0; j < 14; j++)
        #pragma unroll
        for (int i = 0; i < 4; i++) acc[j][i] = 0.f;

    // B-frag base pointer (stride per nt = 8*48*4 uint2)
    const uint2* __restrict__ wbase =
        g_Wp2 + (size_t)(g * NS) * 4 + c2g + (size_t)ntbase * (8 * NS * 4);

    float2 cur[4];
    cur[0] = *reinterpret_cast<const float2*>(pA + c2);
    cur[1] = *reinterpret_cast<const float2*>(pB + c2);
    cur[2] = *reinterpret_cast<const float2*>(pA + 8 + c2);
    cur[3] = *reinterpret_cast<const float2*>(pB + 8 + c2);

    for (int s = 0; s < NS; s++) {
        float2 nxt[4];
        if (s < NS - 1) {
            const int k = (s + 1) * 16;
            nxt[0] = *reinterpret_cast<const float2*>(pA + k + c2);
            nxt[1] = *reinterpret_cast<const float2*>(pB + k + c2);
            nxt[2] = *reinterpret_cast<const float2*>(pA + k + 8 + c2);
            nxt[3] = *reinterpret_cast<const float2*>(pB + k + 8 + c2);
        }

        unsigned ahi[4], alo[4];
        split2h(cur[0].x, cur[0].y, ahi[0], alo[0]);
        split2h(cur[1].x, cur[1].y, ahi[1], alo[1]);
        split2h(cur[2].x, cur[2].y, ahi[2], alo[2]);
        split2h(cur[3].x, cur[3].y, ahi[3], alo[3]);

        const uint2* __restrict__ wp = wbase + s * 4;
        #pragma unroll
        for (int j = 0; j < 14; j++) {
            uint2 bw = __ldg(wp + (size_t)j * (8 * NS * 4));
            unsigned bhi[2] = { bw.x, bw.y };
            mmaf16(acc[j], ahi, bhi);
            mmaf16(acc[j], alo, bhi);
        }

        cur[0] = nxt[0]; cur[1] = nxt[1]; cur[2] = nxt[2]; cur[3] = nxt[3];
    }

    // Epilogue: nt_global = ntbase + j. K: 0..8 (hi only), Q: 9..17 (hi+lo,
    // prescaled), V: 18..26 (fp32)
    const size_t rA = (size_t)(m0 + g);
    const size_t rB = (size_t)(m0 + g + 8);
    #pragma unroll
    for (int j = 0; j < 14; j++) {
        const int ntg   = ntbase + j;
        const int which = ntg / 9;
        const int nb    = ntg - which * 9;
        if (which == 0) {
            const int pp = nb * 4 + c2g;
            g_Kp[rA * HPAIR + pp] = pack_h2(acc[j][0], acc[j][1]);
            g_Kp[rB * HPAIR + pp] = pack_h2(acc[j][2], acc[j][3]);
        } else if (which == 1) {
            const int pp = nb * 4 + c2g;
            float q0 = acc[j][0] * QSCALE, q1 = acc[j][1] * QSCALE;
            float q2 = acc[j][2] * QSCALE, q3 = acc[j][3] * QSCALE;
            unsigned h0, l0v, h1, l1v;
            split2h(q0, q1, h0, l0v);
            split2h(q2, q3, h1, l1v);
            g_Qp_hi[rA * HPAIR + pp] = h0;
            g_Qp_lo[rA * HPAIR + pp] = l0v;
            g_Qp_hi[rB * HPAIR + pp] = h1;
            g_Qp_lo[rB * HPAIR + pp] = l1v;
        } else {
            const int col = nb * 8 + c2;
            *reinterpret_cast<float2*>(&g_V[rA * H + col]) =
                make_float2(acc[j][0], acc[j][1]);
            *reinterpret_cast<float2*>(&g_V[rB * H + col]) =
                make_float2(acc[j][2], acc[j][3]);
        }
    }
}

// ---------------------------------------------------------------------------
// vpack: fp32 V -> fp16x2 token-pairs (hi only), TRANSPOSED layout [b][p][n]
// ---------------------------------------------------------------------------
__global__ __launch_bounds__(256) void vpack_kernel()
{
    int idx = blockIdx.x * 256 + threadIdx.x;
    if (idx >= B * TPAIR * H) return;
    int n   = idx % H;
    int rem = idx / H;
    int p   = rem % TPAIR;
    int b   = rem / TPAIR;
    float v0 = g_V[((size_t)b * T + 2 * p)     * H + n];
    float v1 = g_V[((size_t)b * T + 2 * p + 1) * H + n];
    g_Vp[idx] = pack_h2(v0, v1);
}

// ---------------------------------------------------------------------------
// Tensor-core flash attention, fp16 2-term, smem double-buffered cp.async.
// 128 threads (4 warps), BR=64 (16 rows/warp), BC=64.
// Stage (u32): Kh[64*36]=2304, Vh[32*72]=2304 -> 4608 u32 = 18432 B.
// ---------------------------------------------------------------------------
#define STG_U32 4608
#define VOFF_H  2304

__global__ __launch_bounds__(128) void attn_kernel(float* __restrict__ out)
{
    extern __shared__ unsigned smn[];
    const unsigned smbase = (unsigned)__cvta_generic_to_shared(smn);

    const int qt = (int)(gridDim.x - 1 - blockIdx.x);   // heavy tiles first
    const int b  = blockIdx.y;
    const int t  = threadIdx.x;
    const int w    = t >> 5;
    const int lane = t & 31;
    const int g    = lane >> 2;
    const int li   = lane & 3;

    const int row0 = qt * 64 + w * 16;
    const size_t qbase = (size_t)b * T + row0;

    // ---- Q fragments: load once, keep in registers (hi + lo) ----
    unsigned qhi[5][4], qlo[5][4];
    #pragma unroll
    for (int ks = 0; ks < 5; ks++) {
        if (ks < 4) {
            const int p0 = ks * 8 + li, p1 = ks * 8 + 4 + li;
            qhi[ks][0] = g_Qp_hi[(qbase + g)     * HPAIR + p0];
            qhi[ks][1] = g_Qp_hi[(qbase + g + 8) * HPAIR + p0];
            qhi[ks][2] = g_Qp_hi[(qbase + g)     * HPAIR + p1];
            qhi[ks][3] = g_Qp_hi[(qbase + g + 8) * HPAIR + p1];
            qlo[ks][0] = g_Qp_lo[(qbase + g)     * HPAIR + p0];
            qlo[ks][1] = g_Qp_lo[(qbase + g + 8) * HPAIR + p0];
            qlo[ks][2] = g_Qp_lo[(qbase + g)     * HPAIR + p1];
            qlo[ks][3] = g_Qp_lo[(qbase + g + 8) * HPAIR + p1];
        } else {
            const int p0 = 32 + li;
            qhi[4][0] = g_Qp_hi[(qbase + g)     * HPAIR + p0];
            qhi[4][1] = g_Qp_hi[(qbase + g + 8) * HPAIR + p0];
            qhi[4][2] = 0; qhi[4][3] = 0;
            qlo[4][0] = g_Qp_lo[(qbase + g)     * HPAIR + p0];
            qlo[4][1] = g_Qp_lo[(qbase + g + 8) * HPAIR + p0];
            qlo[4][2] = 0; qlo[4][3] = 0;
        }
    }

    // ---- tile fill via cp.async (2 contiguous 9216B blocks) ----
    auto fill = [&](int stage, int kt) {
        const unsigned dst = smbase + stage * (STG_U32 * 4);
        const char* sK = (const char*)(g_Kp + ((size_t)b * T + kt * 64) * HPAIR);
        const char* sV = (const char*)(g_Vp + ((size_t)b * TPAIR + kt * 32) * H);
        for (int i = t; i < 576; i += 128) {
            const int o = i * 16;
            cp16(dst + o,              sK + o);
            cp16(dst + VOFF_H * 4 + o, sV + o);
        }
    };

    fill(0, 0);
    asm volatile("cp.async.commit_group;\n");

    float m0r = -1e30f, m1r = -1e30f, l0 = 0.f, l1 = 0.f;
    float o[9][4];
    #pragma unroll
    for (int j = 0; j < 9; j++)
        #pragma unroll
        for (int i = 0; i < 4; i++) o[j][i] = 0.f;

    for (int kt = 0; kt <= qt; kt++) {
        if (kt < qt) {
            fill((kt + 1) & 1, kt + 1);
            asm volatile("cp.async.commit_group;\n");
            asm volatile("cp.async.wait_group 1;\n");
        } else {
            asm volatile("cp.async.wait_group 0;\n");
        }
        __syncthreads();

        const unsigned* __restrict__ st = smn + (kt & 1) * STG_U32;
        const unsigned* __restrict__ Kh = st;
        const unsigned* __restrict__ Vh = st + VOFF_H;

        // ---- S = Q K^T : 2 mma per (ks, nb) ----
        float s[8][4];
        #pragma unroll
        for (int nb = 0; nb < 8; nb++)
            #pragma unroll
            for (int i = 0; i < 4; i++) s[nb][i] = 0.f;

        #pragma unroll
        for (int ks = 0; ks < 5; ks++) {
            #pragma unroll
            for (int nb = 0; nb < 8; nb++) {
                const int rk = (nb * 8 + g) * HPAIR;
                unsigned bh[2];
                if (ks < 4) {
                    bh[0] = Kh[rk + ks * 8 + li];
                    bh[1] = Kh[rk + ks * 8 + 4 + li];
                } else {
                    bh[0] = Kh[rk + 32 + li]; bh[1] = 0;
                }
                mmaf16(s[nb], qhi[ks], bh);
                mmaf16(s[nb], qlo[ks], bh);
            }
        }

        // ---- causal mask (diagonal tile only) ----
        if (kt == qt) {
            const int r0g = row0 + g, r1g = row0 + g + 8;
            #pragma unroll
            for (int nb = 0; nb < 8; nb++) {
                const int c = qt * 64 + nb * 8 + 2 * li;
                if (c     > r0g) s[nb][0] = -1e30f;
                if (c + 1 > r0g) s[nb][1] = -1e30f;
                if (c     > r1g) s[nb][2] = -1e30f;
                if (c + 1 > r1g) s[nb][3] = -1e30f;
            }
        }

        // ---- online softmax (quad-replicated state) ----
        float rm0 = -1e30f, rm1 = -1e30f;
        #pragma unroll
        for (int nb = 0; nb < 8; nb++) {
            rm0 = fmaxf(rm0, fmaxf(s[nb][0], s[nb][1]));
            rm1 = fmaxf(rm1, fmaxf(s[nb][2], s[nb][3]));
        }
        rm0 = fmaxf(rm0, __shfl_xor_sync(0xffffffffu, rm0, 1));
        rm0 = fmaxf(rm0, __shfl_xor_sync(0xffffffffu, rm0, 2));
        rm1 = fmaxf(rm1, __shfl_xor_sync(0xffffffffu, rm1, 1));
        rm1 = fmaxf(rm1, __shfl_xor_sync(0xffffffffu, rm1, 2));

        const float mn0 = fmaxf(m0r, rm0);
        const float mn1 = fmaxf(m1r, rm1);
        const float sc0 = __expf(m0r - mn0);
        const float sc1 = __expf(m1r - mn1);

        float rs0 = 0.f, rs1 = 0.f;
        #pragma unroll
        for (int nb = 0; nb < 8; nb++) {
            s[nb][0] = __expf(s[nb][0] - mn0);
            s[nb][1] = __expf(s[nb][1] - mn0);
            s[nb][2] = __expf(s[nb][2] - mn1);
            s[nb][3] = __expf(s[nb][3] - mn1);
            rs0 += s[nb][0] + s[nb][1];
            rs1 += s[nb][2] + s[nb][3];
        }
        rs0 += __shfl_xor_sync(0xffffffffu, rs0, 1);
        rs0 += __shfl_xor_sync(0xffffffffu, rs0, 2);
        rs1 += __shfl_xor_sync(0xffffffffu, rs1, 1);
        rs1 += __shfl_xor_sync(0xffffffffu, rs1, 2);

        l0 = l0 * sc0 + rs0;
        l1 = l1 * sc1 + rs1;
        m0r = mn0; m1r = mn1;

        #pragma unroll
        for (int j = 0; j < 9; j++) {
            o[j][0] *= sc0; o[j][1] *= sc0;
            o[j][2] *= sc1; o[j][3] *= sc1;
        }

        // ---- O += P V : 2 mma per (ks, nb) ----
        #pragma unroll
        for (int ks = 0; ks < 4; ks++) {
            unsigned ph[4], pl[4];
            split2h(s[2*ks][0],   s[2*ks][1],   ph[0], pl[0]);
            split2h(s[2*ks][2],   s[2*ks][3],   ph[1], pl[1]);
            split2h(s[2*ks+1][0], s[2*ks+1][1], ph[2], pl[2]);
            split2h(s[2*ks+1][2], s[2*ks+1][3], ph[3], pl[3]);

            const int rv0 = (ks * 8 + li) * H;
            const int rv1 = (ks * 8 + 4 + li) * H;
            #pragma unroll
            for (int nb = 0; nb < 9; nb++) {
                const int cn = nb * 8 + g;
                unsigned vh[2] = { Vh[rv0 + cn], Vh[rv1 + cn] };
                mmaf16(o[nb], ph, vh);
                mmaf16(o[nb], pl, vh);
            }
        }
        __syncthreads();   // all warps done with this stage before refill
    }

    // ---- epilogue ----
    const float inv0 = 1.f / l0;
    const float inv1 = 1.f / l1;
    float* od0 = out + (qbase + g)     * H;
    float* od1 = out + (qbase + g + 8) * H;
    #pragma unroll
    for (int nb = 0; nb < 9; nb++) {
        const int col = nb * 8 + 2 * li;
        *reinterpret_cast<float2*>(od0 + col) = make_float2(o[nb][0] * inv0, o[nb][1] * inv0);
        *reinterpret_cast<float2*>(od1 + col) = make_float2(o[nb][2] * inv1, o[nb][3] * inv1);
    }
}

// ---------------------------------------------------------------------------
extern "C" void kernel_launch(void* const* d_in, const int* in_sizes, int n_in,
                              void* d_out, int out_size)
{
    const float* x  = (const float*)d_in[0];
    const float* Wk = (const float*)d_in[1];
    const float* Wq = (const float*)d_in[2];
    const float* Wv = (const float*)d_in[3];
    float* out = (float*)d_out;

    prep_w<<<(WPIDX + 255) / 256, 256>>>(Wk, Wq, Wv);
    proj_kernel<<<BT / 64, 256>>>(x);
    vpack_kernel<<<(B * TPAIR * H + 255) / 256, 256>>>();

    cudaFuncSetAttribute(attn_kernel, cudaFuncAttributeMaxDynamicSharedMemorySize, 36864);
    attn_kernel<<<dim3(T / 64, B), 128, 36864>>>(out);
}

// round 15
// speedup vs baseline: 1.7318x; 1.0169x over previous
#include <cuda_runtime.h>
#include <cuda_fp16.h>
#include <stdint.h>
#include <math.h>

#define B 64
#define T 512
#define E 768
#define H 72
#define BT (B*T)

#define NS   48              // k16 steps over K=768
#define NG   216             // total output cols (3*72)
#define WPIDX (NG*NS*4)      // uint2 count in packed W
#define HPAIR 36             // h-pairs per row for packed Q/K
#define TPAIR 256            // token-pairs per batch for packed V

#define QSCALE 0.11785113019775793f   // 1/sqrt(72)

// Scratch (static device globals -- no allocation in kernel_launch)
__device__ unsigned g_Qp_hi[BT*HPAIR];   // fp16x2 h-pairs (A operand: hi+lo)
__device__ unsigned g_Qp_lo[BT*HPAIR];
__device__ unsigned g_Kp[BT*HPAIR];      // fp16x2 h-pairs (B operand: hi only)
// V packed transposed: [b][pair p][n] (hi only), written directly by proj
__device__ __align__(16) unsigned g_Vp[B*TPAIR*H];
// Packed W fragments (hi only): uint2 at index ng*192 + s*4 + c2g
__device__ uint2 g_Wp2[WPIDX];

// ---------------------------------------------------------------------------
__device__ __forceinline__ void mmaf16(float* c, const unsigned* a, const unsigned* b)
{
    asm volatile(
        "mma.sync.aligned.m16n8k16.row.col.f32.f16.f16.f32 "
        "{%0,%1,%2,%3}, {%4,%5,%6,%7}, {%8,%9}, {%0,%1,%2,%3};\n"
        : "+f"(c[0]), "+f"(c[1]), "+f"(c[2]), "+f"(c[3])
        : "r"(a[0]), "r"(a[1]), "r"(a[2]), "r"(a[3]), "r"(b[0]), "r"(b[1]));
}

__device__ __forceinline__ unsigned pack_h2(float a, float b)
{
    __half2 h = __floats2half2_rn(a, b);
    return *reinterpret_cast<unsigned*>(&h);
}
// A-operand split: hi = RN(v), lo = RN(v - hi)  (captures v to ~2^-22)
__device__ __forceinline__ void split2h(float v0, float v1, unsigned& hi, unsigned& lo)
{
    __half2 h = __floats2half2_rn(v0, v1);
    float2 hf = __half22float2(h);
    __half2 l = __floats2half2_rn(v0 - hf.x, v1 - hf.y);
    hi = *reinterpret_cast<unsigned*>(&h);
    lo = *reinterpret_cast<unsigned*>(&l);
}

__device__ __forceinline__ void cp16(unsigned smaddr, const void* gptr)
{
    asm volatile("cp.async.cg.shared.global [%0], [%1], 16;\n"
                 :: "r"(smaddr), "l"(gptr));
}

// ---------------------------------------------------------------------------
// prep_w: pack Wk|Wq|Wv (fp16 hi only) into mma B-fragment layout
// ---------------------------------------------------------------------------
__global__ __launch_bounds__(256) void prep_w(
    const float* __restrict__ Wk,
    const float* __restrict__ Wq,
    const float* __restrict__ Wv)
{
    int idx = blockIdx.x * 256 + threadIdx.x;
    if (idx >= WPIDX) return;
    int c2g = idx & 3;
    int s   = (idx >> 2) % NS;
    int ng  = idx / (4 * NS);
    int which = ng / H;
    int n     = ng - which * H;
    const float* __restrict__ W = (which == 0) ? Wk : ((which == 1) ? Wq : Wv);
    int k = s * 16 + c2g * 2;
    uint2 p;
    p.x = pack_h2(W[(size_t)(k + 0) * H + n], W[(size_t)(k + 1) * H + n]);
    p.y = pack_h2(W[(size_t)(k + 8) * H + n], W[(size_t)(k + 9) * H + n]);
    g_Wp2[idx] = p;
}

// ---------------------------------------------------------------------------
// Fused projection GEMM (K,Q,V) — fp16 2-term, V packed in-epilogue.
// CTA = 64 rows, 8 warps. Warps 0-3: rows (w&3)*16, nt 0..13.
//                        Warps 4-7: same rows,      nt 13..26.
// 2 mma per (k-step, tile): Ahi*Bhi + Alo*Bhi. B frag = uint2 (hi only).
// ---------------------------------------------------------------------------
__global__ __launch_bounds__(256, 2) void proj_kernel(const float* __restrict__ x)
{
    const int t    = threadIdx.x;
    const int wid  = t >> 5;
    const int lane = t & 31;
    const int g    = lane >> 2;
    const int c2   = (lane & 3) * 2;
    const int c2g  = lane & 3;

    const int ntbase = (wid >> 2) * 13;          // 0 or 13
    const int m0 = blockIdx.x * 64 + (wid & 3) * 16;
    const float* __restrict__ pA = x + (size_t)(m0 + g) * E;
    const float* __restrict__ pB = x + (size_t)(m0 + g + 8) * E;

    float acc[14][4];
    #pragma unroll
    for (int j = 0; j < 14; j++)
        #pragma unroll
        for (int i = 0; i < 4; i++) acc[j][i] = 0.f;

    // B-frag base pointer (stride per nt = 8*48*4 uint2)
    const uint2* __restrict__ wbase =
        g_Wp2 + (size_t)(g * NS) * 4 + c2g + (size_t)ntbase * (8 * NS * 4);

    float2 cur[4];
    cur[0] = *reinterpret_cast<const float2*>(pA + c2);
    cur[1] = *reinterpret_cast<const float2*>(pB + c2);
    cur[2] = *reinterpret_cast<const float2*>(pA + 8 + c2);
    cur[3] = *reinterpret_cast<const float2*>(pB + 8 + c2);

    for (int s = 0; s < NS; s++) {
        float2 nxt[4];
        if (s < NS - 1) {
            const int k = (s + 1) * 16;
            nxt[0] = *reinterpret_cast<const float2*>(pA + k + c2);
            nxt[1] = *reinterpret_cast<const float2*>(pB + k + c2);
            nxt[2] = *reinterpret_cast<const float2*>(pA + k + 8 + c2);
            nxt[3] = *reinterpret_cast<const float2*>(pB + k + 8 + c2);
        }

        unsigned ahi[4], alo[4];
        split2h(cur[0].x, cur[0].y, ahi[0], alo[0]);
        split2h(cur[1].x, cur[1].y, ahi[1], alo[1]);
        split2h(cur[2].x, cur[2].y, ahi[2], alo[2]);
        split2h(cur[3].x, cur[3].y, ahi[3], alo[3]);

        const uint2* __restrict__ wp = wbase + s * 4;
        #pragma unroll
        for (int j = 0; j < 14; j++) {
            uint2 bw = __ldg(wp + (size_t)j * (8 * NS * 4));
            unsigned bhi[2] = { bw.x, bw.y };
            mmaf16(acc[j], ahi, bhi);
            mmaf16(acc[j], alo, bhi);
        }

        cur[0] = nxt[0]; cur[1] = nxt[1]; cur[2] = nxt[2]; cur[3] = nxt[3];
    }

    // Epilogue: nt_global = ntbase + j.
    //   K: 0..8 (fp16 hi only), Q: 9..17 (hi+lo, prescaled),
    //   V: 18..26 -> packed token-pairs directly (shfl with row-partner lane).
    const size_t rA = (size_t)(m0 + g);
    const size_t rB = (size_t)(m0 + g + 8);
    #pragma unroll
    for (int j = 0; j < 14; j++) {
        const int ntg   = ntbase + j;
        const int which = ntg / 9;
        const int nb    = ntg - which * 9;
        if (which == 0) {
            const int pp = nb * 4 + c2g;
            g_Kp[rA * HPAIR + pp] = pack_h2(acc[j][0], acc[j][1]);
            g_Kp[rB * HPAIR + pp] = pack_h2(acc[j][2], acc[j][3]);
        } else if (which == 1) {
            const int pp = nb * 4 + c2g;
            float q0 = acc[j][0] * QSCALE, q1 = acc[j][1] * QSCALE;
            float q2 = acc[j][2] * QSCALE, q3 = acc[j][3] * QSCALE;
            unsigned h0, l0v, h1, l1v;
            split2h(q0, q1, h0, l0v);
            split2h(q2, q3, h1, l1v);
            g_Qp_hi[rA * HPAIR + pp] = h0;
            g_Qp_lo[rA * HPAIR + pp] = l0v;
            g_Qp_hi[rB * HPAIR + pp] = h1;
            g_Qp_lo[rB * HPAIR + pp] = l1v;
        } else {
            // partner lane (g^1) holds the adjacent token row
            float pv0 = __shfl_xor_sync(0xffffffffu, acc[j][0], 4);
            float pv1 = __shfl_xor_sync(0xffffffffu, acc[j][1], 4);
            float pv2 = __shfl_xor_sync(0xffffffffu, acc[j][2], 4);
            float pv3 = __shfl_xor_sync(0xffffffffu, acc[j][3], 4);
            if (!(g & 1)) {
                const size_t gp0 = (size_t)(m0 + g) >> 1;       // pair of rows m0+g, m0+g+1
                const size_t gp1 = (size_t)(m0 + g + 8) >> 1;   // pair of rows m0+g+8, m0+g+9
                const int n0 = nb * 8 + c2;
                uint2 w0, w1;
                w0.x = pack_h2(acc[j][0], pv0);
                w0.y = pack_h2(acc[j][1], pv1);
                w1.x = pack_h2(acc[j][2], pv2);
                w1.y = pack_h2(acc[j][3], pv3);
                *reinterpret_cast<uint2*>(&g_Vp[gp0 * H + n0]) = w0;
                *reinterpret_cast<uint2*>(&g_Vp[gp1 * H + n0]) = w1;
            }
        }
    }
}

// ---------------------------------------------------------------------------
// Tensor-core flash attention, fp16 2-term.
// 128 threads (4 warps), BR=64 (16 rows/warp).
// KV staged 128 cols at a time (double-buffered cp.async), consumed in two
// 64-col passes per stage -> half the barriers/fills of the 64-col version.
// Stage (u32): Kh[128*36]=4608, Vh[64*72]=4608 -> 9216 u32 = 36864 B.
// ---------------------------------------------------------------------------
#define STG_U32 9216
#define VOFF    4608

__global__ __launch_bounds__(128) void attn_kernel(float* __restrict__ out)
{
    extern __shared__ unsigned smn[];
    const unsigned smbase = (unsigned)__cvta_generic_to_shared(smn);

    const int qt = (int)(gridDim.x - 1 - blockIdx.x);   // heavy tiles first
    const int b  = blockIdx.y;
    const int t  = threadIdx.x;
    const int w    = t >> 5;
    const int lane = t & 31;
    const int g    = lane >> 2;
    const int li   = lane & 3;

    const int row0 = qt * 64 + w * 16;
    const size_t qbase = (size_t)b * T + row0;

    // ---- Q fragments: load once, keep in registers (hi + lo) ----
    unsigned qhi[5][4], qlo[5][4];
    #pragma unroll
    for (int ks = 0; ks < 5; ks++) {
        if (ks < 4) {
            const int p0 = ks * 8 + li, p1 = ks * 8 + 4 + li;
            qhi[ks][0] = g_Qp_hi[(qbase + g)     * HPAIR + p0];
            qhi[ks][1] = g_Qp_hi[(qbase + g + 8) * HPAIR + p0];
            qhi[ks][2] = g_Qp_hi[(qbase + g)     * HPAIR + p1];
            qhi[ks][3] = g_Qp_hi[(qbase + g + 8) * HPAIR + p1];
            qlo[ks][0] = g_Qp_lo[(qbase + g)     * HPAIR + p0];
            qlo[ks][1] = g_Qp_lo[(qbase + g + 8) * HPAIR + p0];
            qlo[ks][2] = g_Qp_lo[(qbase + g)     * HPAIR + p1];
            qlo[ks][3] = g_Qp_lo[(qbase + g + 8) * HPAIR + p1];
        } else {
            const int p0 = 32 + li;
            qhi[4][0] = g_Qp_hi[(qbase + g)     * HPAIR + p0];
            qhi[4][1] = g_Qp_hi[(qbase + g + 8) * HPAIR + p0];
            qhi[4][2] = 0; qhi[4][3] = 0;
            qlo[4][0] = g_Qp_lo[(qbase + g)     * HPAIR + p0];
            qlo[4][1] = g_Qp_lo[(qbase + g + 8) * HPAIR + p0];
            qlo[4][2] = 0; qlo[4][3] = 0;
        }
    }

    // ---- stage fill: 128 K rows + 64 V pairs, contiguous 18KB blocks ----
    auto fill = [&](int stage, int kt2) {
        const unsigned dst = smbase + stage * (STG_U32 * 4);
        const char* sK = (const char*)(g_Kp + ((size_t)b * T + kt2 * 128) * HPAIR);
        const char* sV = (const char*)(g_Vp + ((size_t)b * TPAIR + kt2 * 64) * H);
        for (int i = t; i < 1152; i += 128) {
            const int o = i * 16;
            cp16(dst + o,            sK + o);
            cp16(dst + VOFF * 4 + o, sV + o);
        }
    };

    const int nkt2 = (qt >> 1) + 1;
    fill(0, 0);
    asm volatile("cp.async.commit_group;\n");

    float m0r = -1e30f, m1r = -1e30f, l0 = 0.f, l1 = 0.f;
    float o[9][4];
    #pragma unroll
    for (int j = 0; j < 9; j++)
        #pragma unroll
        for (int i = 0; i < 4; i++) o[j][i] = 0.f;

    for (int kt2 = 0; kt2 < nkt2; kt2++) {
        if (kt2 + 1 < nkt2) {
            fill((kt2 + 1) & 1, kt2 + 1);
            asm volatile("cp.async.commit_group;\n");
            asm volatile("cp.async.wait_group 1;\n");
        } else {
            asm volatile("cp.async.wait_group 0;\n");
        }
        __syncthreads();

        const unsigned* __restrict__ st = smn + (kt2 & 1) * STG_U32;

        #pragma unroll
        for (int h = 0; h < 2; h++) {
            const int ktc = kt2 * 2 + h;
            if (ktc > qt) break;
            const unsigned* __restrict__ Kh = st + h * (64 * HPAIR);
            const unsigned* __restrict__ Vh = st + VOFF + h * (32 * H);

            // ---- S = Q K^T : 2 mma per (ks, nb) ----
            float s[8][4];
            #pragma unroll
            for (int nb = 0; nb < 8; nb++)
                #pragma unroll
                for (int i = 0; i < 4; i++) s[nb][i] = 0.f;

            #pragma unroll
            for (int ks = 0; ks < 5; ks++) {
                #pragma unroll
                for (int nb = 0; nb < 8; nb++) {
                    const int rk = (nb * 8 + g) * HPAIR;
                    unsigned bh[2];
                    if (ks < 4) {
                        bh[0] = Kh[rk + ks * 8 + li];
                        bh[1] = Kh[rk + ks * 8 + 4 + li];
                    } else {
                        bh[0] = Kh[rk + 32 + li]; bh[1] = 0;
                    }
                    mmaf16(s[nb], qhi[ks], bh);
                    mmaf16(s[nb], qlo[ks], bh);
                }
            }

            // ---- causal mask (diagonal tile only) ----
            if (ktc == qt) {
                const int r0g = row0 + g, r1g = row0 + g + 8;
                #pragma unroll
                for (int nb = 0; nb < 8; nb++) {
                    const int c = ktc * 64 + nb * 8 + 2 * li;
                    if (c     > r0g) s[nb][0] = -1e30f;
                    if (c + 1 > r0g) s[nb][1] = -1e30f;
                    if (c     > r1g) s[nb][2] = -1e30f;
                    if (c + 1 > r1g) s[nb][3] = -1e30f;
                }
            }

            // ---- online softmax (quad-replicated state) ----
            float rm0 = -1e30f, rm1 = -1e30f;
            #pragma unroll
            for (int nb = 0; nb < 8; nb++) {
                rm0 = fmaxf(rm0, fmaxf(s[nb][0], s[nb][1]));
                rm1 = fmaxf(rm1, fmaxf(s[nb][2], s[nb][3]));
            }
            rm0 = fmaxf(rm0, __shfl_xor_sync(0xffffffffu, rm0, 1));
            rm0 = fmaxf(rm0, __shfl_xor_sync(0xffffffffu, rm0, 2));
            rm1 = fmaxf(rm1, __shfl_xor_sync(0xffffffffu, rm1, 1));
            rm1 = fmaxf(rm1, __shfl_xor_sync(0xffffffffu, rm1, 2));

            const float mn0 = fmaxf(m0r, rm0);
            const float mn1 = fmaxf(m1r, rm1);
            const float sc0 = __expf(m0r - mn0);
            const float sc1 = __expf(m1r - mn1);

            float rs0 = 0.f, rs1 = 0.f;
            #pragma unroll
            for (int nb = 0; nb < 8; nb++) {
                s[nb][0] = __expf(s[nb][0] - mn0);
                s[nb][1] = __expf(s[nb][1] - mn0);
                s[nb][2] = __expf(s[nb][2] - mn1);
                s[nb][3] = __expf(s[nb][3] - mn1);
                rs0 += s[nb][0] + s[nb][1];
                rs1 += s[nb][2] + s[nb][3];
            }
            rs0 += __shfl_xor_sync(0xffffffffu, rs0, 1);
            rs0 += __shfl_xor_sync(0xffffffffu, rs0, 2);
            rs1 += __shfl_xor_sync(0xffffffffu, rs1, 1);
            rs1 += __shfl_xor_sync(0xffffffffu, rs1, 2);

            l0 = l0 * sc0 + rs0;
            l1 = l1 * sc1 + rs1;
            m0r = mn0; m1r = mn1;

            #pragma unroll
            for (int j = 0; j < 9; j++) {
                o[j][0] *= sc0; o[j][1] *= sc0;
                o[j][2] *= sc1; o[j][3] *= sc1;
            }

            // ---- O += P V : 2 mma per (ks, nb) ----
            #pragma unroll
            for (int ks = 0; ks < 4; ks++) {
                unsigned ph[4], pl[4];
                split2h(s[2*ks][0],   s[2*ks][1],   ph[0], pl[0]);
                split2h(s[2*ks][2],   s[2*ks][3],   ph[1], pl[1]);
                split2h(s[2*ks+1][0], s[2*ks+1][1], ph[2], pl[2]);
                split2h(s[2*ks+1][2], s[2*ks+1][3], ph[3], pl[3]);

                const int rv0 = (ks * 8 + li) * H;
                const int rv1 = (ks * 8 + 4 + li) * H;
                #pragma unroll
                for (int nb = 0; nb < 9; nb++) {
                    const int cn = nb * 8 + g;
                    unsigned vh[2] = { Vh[rv0 + cn], Vh[rv1 + cn] };
                    mmaf16(o[nb], ph, vh);
                    mmaf16(o[nb], pl, vh);
                }
            }
        }
        __syncthreads();   // all warps done with this stage before refill
    }

    // ---- epilogue ----
    const float inv0 = 1.f / l0;
    const float inv1 = 1.f / l1;
    float* od0 = out + (qbase + g)     * H;
    float* od1 = out + (qbase + g + 8) * H;
    #pragma unroll
    for (int nb = 0; nb < 9; nb++) {
        const int col = nb * 8 + 2 * li;
        *reinterpret_cast<float2*>(od0 + col) = make_float2(o[nb][0] * inv0, o[nb][1] * inv0);
        *reinterpret_cast<float2*>(od1 + col) = make_float2(o[nb][2] * inv1, o[nb][3] * inv1);
    }
}

// ---------------------------------------------------------------------------
extern "C" void kernel_launch(void* const* d_in, const int* in_sizes, int n_in,
                              void* d_out, int out_size)
{
    const float* x  = (const float*)d_in[0];
    const float* Wk = (const float*)d_in[1];
    const float* Wq = (const float*)d_in[2];
    const float* Wv = (const float*)d_in[3];
    float* out = (float*)d_out;

    prep_w<<<(WPIDX + 255) / 256, 256>>>(Wk, Wq, Wv);
    proj_kernel<<<BT / 64, 256>>>(x);

    cudaFuncSetAttribute(attn_kernel, cudaFuncAttributeMaxDynamicSharedMemorySize, 73728);
    attn_kernel<<<dim3(T / 64, B), 128, 73728>>>(out);
}

// round 16
// speedup vs baseline: 1.7481x; 1.0094x over previous
#include <cuda_runtime.h>
#include <cuda_fp16.h>
#include <stdint.h>
#include <math.h>

#define B 64
#define T 512
#define E 768
#define H 72
#define BT (B*T)

#define NS   48              // k16 steps over K=768
#define NG   216             // total output cols (3*72)
#define WPIDX (NG*NS*4)      // uint2 count in packed W
#define HPAIR 36             // h-pairs per row for packed Q/K
#define TPAIR 256            // token-pairs per batch for packed V

#define QSCALE 0.11785113019775793f   // 1/sqrt(72)

// Scratch (static device globals -- no allocation in kernel_launch)
__device__ unsigned g_Qp_hi[BT*HPAIR];   // fp16x2 h-pairs (A operand: hi+lo)
__device__ unsigned g_Qp_lo[BT*HPAIR];
__device__ unsigned g_Kp[BT*HPAIR];      // fp16x2 h-pairs (B operand: hi only)
// V packed transposed: [b][pair p][n] (hi only), written directly by proj
__device__ __align__(16) unsigned g_Vp[B*TPAIR*H];
// Packed W fragments (hi only): uint2 at index ng*192 + s*4 + c2g
__device__ uint2 g_Wp2[WPIDX];

// ---------------------------------------------------------------------------
__device__ __forceinline__ void mmaf16(float* c, const unsigned* a, const unsigned* b)
{
    asm volatile(
        "mma.sync.aligned.m16n8k16.row.col.f32.f16.f16.f32 "
        "{%0,%1,%2,%3}, {%4,%5,%6,%7}, {%8,%9}, {%0,%1,%2,%3};\n"
        : "+f"(c[0]), "+f"(c[1]), "+f"(c[2]), "+f"(c[3])
        : "r"(a[0]), "r"(a[1]), "r"(a[2]), "r"(a[3]), "r"(b[0]), "r"(b[1]));
}

__device__ __forceinline__ unsigned pack_h2(float a, float b)
{
    __half2 h = __floats2half2_rn(a, b);
    return *reinterpret_cast<unsigned*>(&h);
}
// A-operand split: hi = RN(v), lo = RN(v - hi)  (captures v to ~2^-22)
__device__ __forceinline__ void split2h(float v0, float v1, unsigned& hi, unsigned& lo)
{
    __half2 h = __floats2half2_rn(v0, v1);
    float2 hf = __half22float2(h);
    __half2 l = __floats2half2_rn(v0 - hf.x, v1 - hf.y);
    hi = *reinterpret_cast<unsigned*>(&h);
    lo = *reinterpret_cast<unsigned*>(&l);
}

__device__ __forceinline__ void cp16(unsigned smaddr, const void* gptr)
{
    asm volatile("cp.async.cg.shared.global [%0], [%1], 16;\n"
                 :: "r"(smaddr), "l"(gptr));
}

// ---------------------------------------------------------------------------
// prep_w: pack Wk|Wq|Wv (fp16 hi only) into mma B-fragment layout
// ---------------------------------------------------------------------------
__global__ __launch_bounds__(256) void prep_w(
    const float* __restrict__ Wk,
    const float* __restrict__ Wq,
    const float* __restrict__ Wv)
{
    int idx = blockIdx.x * 256 + threadIdx.x;
    if (idx >= WPIDX) return;
    int c2g = idx & 3;
    int s   = (idx >> 2) % NS;
    int ng  = idx / (4 * NS);
    int which = ng / H;
    int n     = ng - which * H;
    const float* __restrict__ W = (which == 0) ? Wk : ((which == 1) ? Wq : Wv);
    int k = s * 16 + c2g * 2;
    uint2 p;
    p.x = pack_h2(W[(size_t)(k + 0) * H + n], W[(size_t)(k + 1) * H + n]);
    p.y = pack_h2(W[(size_t)(k + 8) * H + n], W[(size_t)(k + 9) * H + n]);
    g_Wp2[idx] = p;
}

// ---------------------------------------------------------------------------
// Fused projection GEMM (K,Q,V) — fp16 SINGLE-term (x hi only), V packed
// in-epilogue. CTA = 64 rows, 8 warps. Warps 0-3: rows (w&3)*16, nt 0..13;
// warps 4-7: same rows, nt 13..26. 1 mma per (k-step, tile).
// ---------------------------------------------------------------------------
__global__ __launch_bounds__(256, 2) void proj_kernel(const float* __restrict__ x)
{
    const int t    = threadIdx.x;
    const int wid  = t >> 5;
    const int lane = t & 31;
    const int g    = lane >> 2;
    const int c2   = (lane & 3) * 2;
    const int c2g  = lane & 3;

    const int ntbase = (wid >> 2) * 13;          // 0 or 13
    const int m0 = blockIdx.x * 64 + (wid & 3) * 16;
    const float* __restrict__ pA = x + (size_t)(m0 + g) * E;
    const float* __restrict__ pB = x + (size_t)(m0 + g + 8) * E;

    float acc[14][4];
    #pragma unroll
    for (int j = 0; j < 14; j++)
        #pragma unroll
        for (int i = 0; i < 4; i++) acc[j][i] = 0.f;

    // B-frag base pointer (stride per nt = 8*48*4 uint2)
    const uint2* __restrict__ wbase =
        g_Wp2 + (size_t)(g * NS) * 4 + c2g + (size_t)ntbase * (8 * NS * 4);

    float2 cur[4];
    cur[0] = *reinterpret_cast<const float2*>(pA + c2);
    cur[1] = *reinterpret_cast<const float2*>(pB + c2);
    cur[2] = *reinterpret_cast<const float2*>(pA + 8 + c2);
    cur[3] = *reinterpret_cast<const float2*>(pB + 8 + c2);

    for (int s = 0; s < NS; s++) {
        float2 nxt[4];
        if (s < NS - 1) {
            const int k = (s + 1) * 16;
            nxt[0] = *reinterpret_cast<const float2*>(pA + k + c2);
            nxt[1] = *reinterpret_cast<const float2*>(pB + k + c2);
            nxt[2] = *reinterpret_cast<const float2*>(pA + k + 8 + c2);
            nxt[3] = *reinterpret_cast<const float2*>(pB + k + 8 + c2);
        }

        unsigned ahi[4];
        ahi[0] = pack_h2(cur[0].x, cur[0].y);
        ahi[1] = pack_h2(cur[1].x, cur[1].y);
        ahi[2] = pack_h2(cur[2].x, cur[2].y);
        ahi[3] = pack_h2(cur[3].x, cur[3].y);

        const uint2* __restrict__ wp = wbase + s * 4;
        #pragma unroll
        for (int j = 0; j < 14; j++) {
            uint2 bw = __ldg(wp + (size_t)j * (8 * NS * 4));
            unsigned bhi[2] = { bw.x, bw.y };
            mmaf16(acc[j], ahi, bhi);
        }

        cur[0] = nxt[0]; cur[1] = nxt[1]; cur[2] = nxt[2]; cur[3] = nxt[3];
    }

    // Epilogue: nt_global = ntbase + j.
    //   K: 0..8 (fp16 hi only), Q: 9..17 (hi+lo of RESULT, prescaled),
    //   V: 18..26 -> packed token-pairs directly (shfl with row-partner lane).
    const size_t rA = (size_t)(m0 + g);
    const size_t rB = (size_t)(m0 + g + 8);
    #pragma unroll
    for (int j = 0; j < 14; j++) {
        const int ntg   = ntbase + j;
        const int which = ntg / 9;
        const int nb    = ntg - which * 9;
        if (which == 0) {
            const int pp = nb * 4 + c2g;
            g_Kp[rA * HPAIR + pp] = pack_h2(acc[j][0], acc[j][1]);
            g_Kp[rB * HPAIR + pp] = pack_h2(acc[j][2], acc[j][3]);
        } else if (which == 1) {
            const int pp = nb * 4 + c2g;
            float q0 = acc[j][0] * QSCALE, q1 = acc[j][1] * QSCALE;
            float q2 = acc[j][2] * QSCALE, q3 = acc[j][3] * QSCALE;
            unsigned h0, l0v, h1, l1v;
            split2h(q0, q1, h0, l0v);
            split2h(q2, q3, h1, l1v);
            g_Qp_hi[rA * HPAIR + pp] = h0;
            g_Qp_lo[rA * HPAIR + pp] = l0v;
            g_Qp_hi[rB * HPAIR + pp] = h1;
            g_Qp_lo[rB * HPAIR + pp] = l1v;
        } else {
            // partner lane (g^1) holds the adjacent token row
            float pv0 = __shfl_xor_sync(0xffffffffu, acc[j][0], 4);
            float pv1 = __shfl_xor_sync(0xffffffffu, acc[j][1], 4);
            float pv2 = __shfl_xor_sync(0xffffffffu, acc[j][2], 4);
            float pv3 = __shfl_xor_sync(0xffffffffu, acc[j][3], 4);
            if (!(g & 1)) {
                const size_t gp0 = (size_t)(m0 + g) >> 1;       // pair of rows m0+g, m0+g+1
                const size_t gp1 = (size_t)(m0 + g + 8) >> 1;   // pair of rows m0+g+8, m0+g+9
                const int n0 = nb * 8 + c2;
                uint2 w0, w1;
                w0.x = pack_h2(acc[j][0], pv0);
                w0.y = pack_h2(acc[j][1], pv1);
                w1.x = pack_h2(acc[j][2], pv2);
                w1.y = pack_h2(acc[j][3], pv3);
                *reinterpret_cast<uint2*>(&g_Vp[gp0 * H + n0]) = w0;
                *reinterpret_cast<uint2*>(&g_Vp[gp1 * H + n0]) = w1;
            }
        }
    }
}

// ---------------------------------------------------------------------------
// Tensor-core flash attention, fp16 2-term.
// 128 threads (4 warps), BR=64 (16 rows/warp).
// KV staged 128 cols at a time (double-buffered cp.async), consumed in two
// 64-col passes per stage. Stage: Kh[128*36] + Vh[64*72] = 9216 u32 = 36864 B.
// ---------------------------------------------------------------------------
#define STG_U32 9216
#define VOFF    4608

__global__ __launch_bounds__(128) void attn_kernel(float* __restrict__ out)
{
    extern __shared__ unsigned smn[];
    const unsigned smbase = (unsigned)__cvta_generic_to_shared(smn);

    const int qt = (int)(gridDim.x - 1 - blockIdx.x);   // heavy tiles first
    const int b  = blockIdx.y;
    const int t  = threadIdx.x;
    const int w    = t >> 5;
    const int lane = t & 31;
    const int g    = lane >> 2;
    const int li   = lane & 3;

    const int row0 = qt * 64 + w * 16;
    const size_t qbase = (size_t)b * T + row0;

    // ---- Q fragments: load once, keep in registers (hi + lo) ----
    unsigned qhi[5][4], qlo[5][4];
    #pragma unroll
    for (int ks = 0; ks < 5; ks++) {
        if (ks < 4) {
            const int p0 = ks * 8 + li, p1 = ks * 8 + 4 + li;
            qhi[ks][0] = g_Qp_hi[(qbase + g)     * HPAIR + p0];
            qhi[ks][1] = g_Qp_hi[(qbase + g + 8) * HPAIR + p0];
            qhi[ks][2] = g_Qp_hi[(qbase + g)     * HPAIR + p1];
            qhi[ks][3] = g_Qp_hi[(qbase + g + 8) * HPAIR + p1];
            qlo[ks][0] = g_Qp_lo[(qbase + g)     * HPAIR + p0];
            qlo[ks][1] = g_Qp_lo[(qbase + g + 8) * HPAIR + p0];
            qlo[ks][2] = g_Qp_lo[(qbase + g)     * HPAIR + p1];
            qlo[ks][3] = g_Qp_lo[(qbase + g + 8) * HPAIR + p1];
        } else {
            const int p0 = 32 + li;
            qhi[4][0] = g_Qp_hi[(qbase + g)     * HPAIR + p0];
            qhi[4][1] = g_Qp_hi[(qbase + g + 8) * HPAIR + p0];
            qhi[4][2] = 0; qhi[4][3] = 0;
            qlo[4][0] = g_Qp_lo[(qbase + g)     * HPAIR + p0];
            qlo[4][1] = g_Qp_lo[(qbase + g + 8) * HPAIR + p0];
            qlo[4][2] = 0; qlo[4][3] = 0;
        }
    }

    // ---- stage fill: 128 K rows + 64 V pairs, contiguous 18KB blocks ----
    auto fill = [&](int stage, int kt2) {
        const unsigned dst = smbase + stage * (STG_U32 * 4);
        const char* sK = (const char*)(g_Kp + ((size_t)b * T + kt2 * 128) * HPAIR);
        const char* sV = (const char*)(g_Vp + ((size_t)b * TPAIR + kt2 * 64) * H);
        for (int i = t; i < 1152; i += 128) {
            const int o = i * 16;
            cp16(dst + o,            sK + o);
            cp16(dst + VOFF * 4 + o, sV + o);
        }
    };

    const int nkt2 = (qt >> 1) + 1;
    fill(0, 0);
    asm volatile("cp.async.commit_group;\n");

    float m0r = -1e30f, m1r = -1e30f, l0 = 0.f, l1 = 0.f;
    float o[9][4];
    #pragma unroll
    for (int j = 0; j < 9; j++)
        #pragma unroll
        for (int i = 0; i < 4; i++) o[j][i] = 0.f;

    for (int kt2 = 0; kt2 < nkt2; kt2++) {
        if (kt2 + 1 < nkt2) {
            fill((kt2 + 1) & 1, kt2 + 1);
            asm volatile("cp.async.commit_group;\n");
            asm volatile("cp.async.wait_group 1;\n");
        } else {
            asm volatile("cp.async.wait_group 0;\n");
        }
        __syncthreads();

        const unsigned* __restrict__ st = smn + (kt2 & 1) * STG_U32;

        #pragma unroll
        for (int h = 0; h < 2; h++) {
            const int ktc = kt2 * 2 + h;
            if (ktc > qt) break;
            const unsigned* __restrict__ Kh = st + h * (64 * HPAIR);
            const unsigned* __restrict__ Vh = st + VOFF + h * (32 * H);

            // ---- S = Q K^T : 2 mma per (ks, nb) ----
            float s[8][4];
            #pragma unroll
            for (int nb = 0; nb < 8; nb++)
                #pragma unroll
                for (int i = 0; i < 4; i++) s[nb][i] = 0.f;

            #pragma unroll
            for (int ks = 0; ks < 5; ks++) {
                #pragma unroll
                for (int nb = 0; nb < 8; nb++) {
                    const int rk = (nb * 8 + g) * HPAIR;
                    unsigned bh[2];
                    if (ks < 4) {
                        bh[0] = Kh[rk + ks * 8 + li];
                        bh[1] = Kh[rk + ks * 8 + 4 + li];
                    } else {
                        bh[0] = Kh[rk + 32 + li]; bh[1] = 0;
                    }
                    mmaf16(s[nb], qhi[ks], bh);
                    mmaf16(s[nb], qlo[ks], bh);
                }
            }

            // ---- causal mask (diagonal tile only) ----
            if (ktc == qt) {
                const int r0g = row0 + g, r1g = row0 + g + 8;
                #pragma unroll
                for (int nb = 0; nb < 8; nb++) {
                    const int c = ktc * 64 + nb * 8 + 2 * li;
                    if (c     > r0g) s[nb][0] = -1e30f;
                    if (c + 1 > r0g) s[nb][1] = -1e30f;
                    if (c     > r1g) s[nb][2] = -1e30f;
                    if (c + 1 > r1g) s[nb][3] = -1e30f;
                }
            }

            // ---- online softmax (quad-replicated state) ----
            float rm0 = -1e30f, rm1 = -1e30f;
            #pragma unroll
            for (int nb = 0; nb < 8; nb++) {
                rm0 = fmaxf(rm0, fmaxf(s[nb][0], s[nb][1]));
                rm1 = fmaxf(rm1, fmaxf(s[nb][2], s[nb][3]));
            }
            rm0 = fmaxf(rm0, __shfl_xor_sync(0xffffffffu, rm0, 1));
            rm0 = fmaxf(rm0, __shfl_xor_sync(0xffffffffu, rm0, 2));
            rm1 = fmaxf(rm1, __shfl_xor_sync(0xffffffffu, rm1, 1));
            rm1 = fmaxf(rm1, __shfl_xor_sync(0xffffffffu, rm1, 2));

            const float mn0 = fmaxf(m0r, rm0);
            const float mn1 = fmaxf(m1r, rm1);
            const float sc0 = __expf(m0r - mn0);
            const float sc1 = __expf(m1r - mn1);

            float rs0 = 0.f, rs1 = 0.f;
            #pragma unroll
            for (int nb = 0; nb < 8; nb++) {
                s[nb][0] = __expf(s[nb][0] - mn0);
                s[nb][1] = __expf(s[nb][1] - mn0);
                s[nb][2] = __expf(s[nb][2] - mn1);
                s[nb][3] = __expf(s[nb][3] - mn1);
                rs0 += s[nb][0] + s[nb][1];
                rs1 += s[nb][2] + s[nb][3];
            }
            rs0 += __shfl_xor_sync(0xffffffffu, rs0, 1);
            rs0 += __shfl_xor_sync(0xffffffffu, rs0, 2);
            rs1 += __shfl_xor_sync(0xffffffffu, rs1, 1);
            rs1 += __shfl_xor_sync(0xffffffffu, rs1, 2);

            l0 = l0 * sc0 + rs0;
            l1 = l1 * sc1 + rs1;
            m0r = mn0; m1r = mn1;

            #pragma unroll
            for (int j = 0; j < 9; j++) {
                o[j][0] *= sc0; o[j][1] *= sc0;
                o[j][2] *= sc1; o[j][3] *= sc1;
            }

            // ---- O += P V : 2 mma per (ks, nb) ----
            #pragma unroll
            for (int ks = 0; ks < 4; ks++) {
                unsigned ph[4], pl[4];
                split2h(s[2*ks][0],   s[2*ks][1],   ph[0], pl[0]);
                split2h(s[2*ks][2],   s[2*ks][3],   ph[1], pl[1]);
                split2h(s[2*ks+1][0], s[2*ks+1][1], ph[2], pl[2]);
                split2h(s[2*ks+1][2], s[2*ks+1][3], ph[3], pl[3]);

                const int rv0 = (ks * 8 + li) * H;
                const int rv1 = (ks * 8 + 4 + li) * H;
                #pragma unroll
                for (int nb = 0; nb < 9; nb++) {
                    const int cn = nb * 8 + g;
                    unsigned vh[2] = { Vh[rv0 + cn], Vh[rv1 + cn] };
                    mmaf16(o[nb], ph, vh);
                    mmaf16(o[nb], pl, vh);
                }
            }
        }
        __syncthreads();   // all warps done with this stage before refill
    }

    // ---- epilogue ----
    const float inv0 = 1.f / l0;
    const float inv1 = 1.f / l1;
    float* od0 = out + (qbase + g)     * H;
    float* od1 = out + (qbase + g + 8) * H;
    #pragma unroll
    for (int nb = 0; nb < 9; nb++) {
        const int col = nb * 8 + 2 * li;
        *reinterpret_cast<float2*>(od0 + col) = make_float2(o[nb][0] * inv0, o[nb][1] * inv0);
        *reinterpret_cast<float2*>(od1 + col) = make_float2(o[nb][2] * inv1, o[nb][3] * inv1);
    }
}

// ---------------------------------------------------------------------------
extern "C" void kernel_launch(void* const* d_in, const int* in_sizes, int n_in,
                              void* d_out, int out_size)
{
    const float* x  = (const float*)d_in[0];
    const float* Wk = (const float*)d_in[1];
    const float* Wq = (const float*)d_in[2];
    const float* Wv = (const float*)d_in[3];
    float* out = (float*)d_out;

    prep_w<<<(WPIDX + 255) / 256, 256>>>(Wk, Wq, Wv);
    proj_kernel<<<BT / 64, 256>>>(x);

    cudaFuncSetAttribute(attn_kernel, cudaFuncAttributeMaxDynamicSharedMemorySize, 73728);
    attn_kernel<<<dim3(T / 64, B), 128, 73728>>>(out);
}